// round 15
// baseline (speedup 1.0000x reference)
#include <cuda_runtime.h>
#include <cuda_bf16.h>
#include <cstdint>

#define NB 2
#define AB 1344
#define LB 96
#define ATOMS 14
#define DB 128
#define HB 8
#define DEPTH 3
#define RB (NB*AB)      /* 2688 */
#define EB (HB*DB)      /* 1024 */
#define WORDS (AB/32)   /* 42 */
#define ATILE 64
#define LDSB 136
#define GSMEM (384*LDSB*2)          /* 104448: Ahi+Alo (128 rows ea) + B (128 rows) */
#define ESMEM (16*EB*4)             /* 65536: 16 rows of g_fp */

#define PACK_BLKS ((NB*AB*WORDS)/8) /* 14112 */
#define CONVW_N4 (DEPTH*EB*DB/4)
#define CONVW_BLKS ((CONVW_N4+255)/256)
#define CONVX_N4 (RB*DB/4)
#define CONVX_BLKS ((CONVX_N4+255)/256)
#define OUTZ_N4 (NB*LB*DB/4)        /* 6144 */
#define OUTZ_BLKS ((OUTZ_N4+255)/256)

// ---------------- scratch ----------------
__device__ float  g_fp[RB*EB];
__device__ float  g_x0[RB*DB];
__device__ float  g_x1[RB*DB];
__device__ __nv_bfloat16 g_xhi[RB*DB];
__device__ __nv_bfloat16 g_xlo[RB*DB];
__device__ __nv_bfloat16 g_whi[DEPTH*EB*DB];
__device__ __nv_bfloat16 g_wlo[DEPTH*EB*DB];
__device__ float  g_es [NB*HB*AB];
__device__ float  g_es2[NB*HB*AB];
__device__ float2 g_PQ [NB*HB*AB];
__device__ float  g_diag[NB*HB*AB];
__device__ unsigned g_ebits[NB*AB*WORDS];

#define LDSM4(r0,r1,r2,r3,addr) asm volatile( \
  "ldmatrix.sync.aligned.m8n8.x4.shared.b16 {%0,%1,%2,%3}, [%4];" \
  : "=r"(r0),"=r"(r1),"=r"(r2),"=r"(r3) : "r"(addr))

#define MMA_BF16(c,a0,a1,a2,a3,b0,b1) asm volatile( \
  "mma.sync.aligned.m16n8k16.row.col.f32.bf16.bf16.f32 " \
  "{%0,%1,%2,%3},{%4,%5,%6,%7},{%8,%9},{%0,%1,%2,%3};" \
  : "+f"(c[0]),"+f"(c[1]),"+f"(c[2]),"+f"(c[3]) \
  : "r"(a0),"r"(a1),"r"(a2),"r"(a3),"r"(b0),"r"(b1))

#define CP16(dst_u32, src_ptr) asm volatile( \
  "cp.async.cg.shared.global [%0], [%1], 16;" :: "r"(dst_u32), "l"(src_ptr))

__device__ __forceinline__ unsigned su32(const void* p) {
    unsigned a;
    asm("{ .reg .u64 t; cvta.to.shared.u64 t, %1; cvt.u32.u64 %0, t; }" : "=r"(a) : "l"(p));
    return a;
}

// ---------------- fused setup: pack edges + hi/lo convs + zero out ----------------
__device__ __forceinline__ void conv4(const float* __restrict__ src,
                                      __nv_bfloat16* __restrict__ hi,
                                      __nv_bfloat16* __restrict__ lo, int idx) {
    float4 v = ((const float4*)src)[idx];
    __nv_bfloat16 h0 = __float2bfloat16(v.x), h1 = __float2bfloat16(v.y);
    __nv_bfloat16 h2 = __float2bfloat16(v.z), h3 = __float2bfloat16(v.w);
    __nv_bfloat16 l0 = __float2bfloat16(v.x - __bfloat162float(h0));
    __nv_bfloat16 l1 = __float2bfloat16(v.y - __bfloat162float(h1));
    __nv_bfloat16 l2 = __float2bfloat16(v.z - __bfloat162float(h2));
    __nv_bfloat16 l3 = __float2bfloat16(v.w - __bfloat162float(h3));
    ((__nv_bfloat162*)hi)[idx*2]   = __halves2bfloat162(h0, h1);
    ((__nv_bfloat162*)hi)[idx*2+1] = __halves2bfloat162(h2, h3);
    ((__nv_bfloat162*)lo)[idx*2]   = __halves2bfloat162(l0, l1);
    ((__nv_bfloat162*)lo)[idx*2+1] = __halves2bfloat162(l2, l3);
}

__global__ void setup_k(const unsigned* __restrict__ em, const float* __restrict__ W,
                        const float* __restrict__ feats,
                        __nv_bfloat16* __restrict__ whi, __nv_bfloat16* __restrict__ wlo,
                        __nv_bfloat16* __restrict__ xhi, __nv_bfloat16* __restrict__ xlo,
                        float* __restrict__ out) {
    int b = blockIdx.x;
    int tid = threadIdx.x;
    if (b < PACK_BLKS) {
        int w = b * 8 + (tid >> 5);
        int lane = tid & 31;
        unsigned v = em[(size_t)w * 32 + lane];
        unsigned m = __ballot_sync(0xffffffffu, v != 0u);
        if (lane == 0) g_ebits[w] = m;
    } else if (b < PACK_BLKS + CONVW_BLKS) {
        int idx = (b - PACK_BLKS) * 256 + tid;
        if (idx < CONVW_N4) conv4(W, whi, wlo, idx);
    } else if (b < PACK_BLKS + CONVW_BLKS + CONVX_BLKS) {
        int idx = (b - PACK_BLKS - CONVW_BLKS) * 256 + tid;
        if (idx < CONVX_N4) conv4(feats, xhi, xlo, idx);
    } else {
        int idx = (b - PACK_BLKS - CONVW_BLKS - CONVX_BLKS) * 256 + tid;
        if (idx < OUTZ_N4) ((float4*)out)[idx] = make_float4(0.f, 0.f, 0.f, 0.f);
    }
}

// ---------------- TC GEMM: 128 rows x 128 cols (one head), B reloaded hi->lo ----------------
__global__ void __launch_bounds__(256, 2) gemm_fp_k(
    const __nv_bfloat16* __restrict__ Xhi, const __nv_bfloat16* __restrict__ Xlo,
    const __nv_bfloat16* __restrict__ Whi, const __nv_bfloat16* __restrict__ Wlo,
    const int* __restrict__ mask,
    const float* __restrict__ ssrc, const float* __restrict__ stag)
{
    extern __shared__ __nv_bfloat16 sm[];
    __nv_bfloat16* Ahi = sm;
    __nv_bfloat16* Alo = sm + 128 * LDSB;
    __nv_bfloat16* Bb  = sm + 256 * LDSB;
    __shared__ float sws[128], swt[128];
    __shared__ float sredPs[2][128], sredPt[2][128];

    int tid = threadIdx.x;
    int rowBase = blockIdx.x * 128;
    int h = blockIdx.y;
    int colBase = h * DB;

    if (tid < 128) { sws[tid] = ssrc[colBase + tid]; swt[tid] = stag[colBase + tid]; }

    unsigned sAhi = (unsigned)__cvta_generic_to_shared(Ahi);
    unsigned sAlo = (unsigned)__cvta_generic_to_shared(Alo);
    unsigned sB   = (unsigned)__cvta_generic_to_shared(Bb);

    // stage A hi/lo (128x128 each) + B = Whi (128x128); 2048 chunks each
#pragma unroll
    for (int i = 0; i < 8; i++) {
        int c = tid + i * 256;
        int r = c >> 4, col = (c & 15) * 8;
        unsigned so = (r * LDSB + col) * 2;
        CP16(sAhi + so, Xhi + (size_t)(rowBase + r) * 128 + col);
        CP16(sAlo + so, Xlo + (size_t)(rowBase + r) * 128 + col);
        CP16(sB + so, Whi + (size_t)(h * 128 + r) * 128 + col);
    }
    asm volatile("cp.async.commit_group;");
    asm volatile("cp.async.wait_group 0;");
    __syncthreads();

    int wid = tid >> 5, lane = tid & 31;
    int warpRow = wid & 3, warpCol = wid >> 2;
    int gq = lane >> 2, tig = lane & 3;

    unsigned aoff = ((warpRow * 16 + (lane & 15)) * LDSB + (lane >> 4) * 8) * 2;
    unsigned boff = ((warpCol * 64 + (lane & 7) + (lane >> 4) * 8) * LDSB
                     + ((lane >> 3) & 1) * 8) * 2;
    unsigned aHi0 = sAhi + aoff, aHi1 = aHi0 + 64 * LDSB * 2;
    unsigned aLo0 = sAlo + aoff, aLo1 = aLo0 + 64 * LDSB * 2;
    unsigned bB   = sB + boff;

    float c0[8][4], c1[8][4];
#pragma unroll
    for (int t = 0; t < 8; t++)
#pragma unroll
        for (int j = 0; j < 4; j++) { c0[t][j] = 0.f; c1[t][j] = 0.f; }

    // pass 1: B = Whi;  (Ahi + Alo) * Bhi for both row tiles
#pragma unroll
    for (int ks = 0; ks < 8; ks++) {
        unsigned kb = ks * 32;
        unsigned h00, h01, h02, h03, h10, h11, h12, h13;
        unsigned l00, l01, l02, l03, l10, l11, l12, l13;
        LDSM4(h00, h01, h02, h03, aHi0 + kb);
        LDSM4(h10, h11, h12, h13, aHi1 + kb);
        LDSM4(l00, l01, l02, l03, aLo0 + kb);
        LDSM4(l10, l11, l12, l13, aLo1 + kb);
        unsigned bh[16];
#pragma unroll
        for (int g4 = 0; g4 < 4; g4++) {
            unsigned off = g4 * 16 * LDSB * 2 + kb;
            LDSM4(bh[g4*4], bh[g4*4+1], bh[g4*4+2], bh[g4*4+3], bB + off);
        }
#pragma unroll
        for (int t = 0; t < 8; t++) {
            int bi = (t >> 1) * 4 + (t & 1) * 2;
            MMA_BF16(c0[t], h00, h01, h02, h03, bh[bi], bh[bi+1]);
            MMA_BF16(c0[t], l00, l01, l02, l03, bh[bi], bh[bi+1]);
            MMA_BF16(c1[t], h10, h11, h12, h13, bh[bi], bh[bi+1]);
            MMA_BF16(c1[t], l10, l11, l12, l13, bh[bi], bh[bi+1]);
        }
    }
    __syncthreads();

    // reload B = Wlo
#pragma unroll
    for (int i = 0; i < 8; i++) {
        int cc = tid + i * 256;
        int r = cc >> 4, col = (cc & 15) * 8;
        CP16(sB + (r * LDSB + col) * 2, Wlo + (size_t)(h * 128 + r) * 128 + col);
    }
    asm volatile("cp.async.commit_group;");
    asm volatile("cp.async.wait_group 0;");
    __syncthreads();

    // pass 2: Ahi * Blo for both row tiles
#pragma unroll
    for (int ks = 0; ks < 8; ks++) {
        unsigned kb = ks * 32;
        unsigned h00, h01, h02, h03, h10, h11, h12, h13;
        LDSM4(h00, h01, h02, h03, aHi0 + kb);
        LDSM4(h10, h11, h12, h13, aHi1 + kb);
        unsigned bh[16];
#pragma unroll
        for (int g4 = 0; g4 < 4; g4++) {
            unsigned off = g4 * 16 * LDSB * 2 + kb;
            LDSM4(bh[g4*4], bh[g4*4+1], bh[g4*4+2], bh[g4*4+3], bB + off);
        }
#pragma unroll
        for (int t = 0; t < 8; t++) {
            int bi = (t >> 1) * 4 + (t & 1) * 2;
            MMA_BF16(c0[t], h00, h01, h02, h03, bh[bi], bh[bi+1]);
            MMA_BF16(c1[t], h10, h11, h12, h13, bh[bi], bh[bi+1]);
        }
    }

    // epilogue: 4 rows per thread (tile0: r0, r0+8; tile1: +64)
    int r0 = rowBase + warpRow * 16 + gq;
    float m0  = (mask[r0]      != 0) ? 1.f : 0.f;
    float m0b = (mask[r0 + 8]  != 0) ? 1.f : 0.f;
    float m1  = (mask[r0 + 64] != 0) ? 1.f : 0.f;
    float m1b = (mask[r0 + 72] != 0) ? 1.f : 0.f;
    float ps0 = 0.f, pt0 = 0.f, ps0b = 0.f, pt0b = 0.f;
    float ps1 = 0.f, pt1 = 0.f, ps1b = 0.f, pt1b = 0.f;
#pragma unroll
    for (int t = 0; t < 8; t++) {
        int cl = warpCol * 64 + t * 8 + tig * 2;
        float w0s = sws[cl], w1s = sws[cl+1], w0t = swt[cl], w1t = swt[cl+1];
        float a0 = c0[t][0] * m0,  a1 = c0[t][1] * m0;
        float a2 = c0[t][2] * m0b, a3 = c0[t][3] * m0b;
        float b0 = c1[t][0] * m1,  b1 = c1[t][1] * m1;
        float b2 = c1[t][2] * m1b, b3 = c1[t][3] * m1b;
        ps0  += a0 * w0s + a1 * w1s;  pt0  += a0 * w0t + a1 * w1t;
        ps0b += a2 * w0s + a3 * w1s;  pt0b += a2 * w0t + a3 * w1t;
        ps1  += b0 * w0s + b1 * w1s;  pt1  += b0 * w0t + b1 * w1t;
        ps1b += b2 * w0s + b3 * w1s;  pt1b += b2 * w0t + b3 * w1t;
        *(float2*)&g_fp[(size_t)r0        * EB + colBase + cl] = make_float2(a0, a1);
        *(float2*)&g_fp[(size_t)(r0 + 8)  * EB + colBase + cl] = make_float2(a2, a3);
        *(float2*)&g_fp[(size_t)(r0 + 64) * EB + colBase + cl] = make_float2(b0, b1);
        *(float2*)&g_fp[(size_t)(r0 + 72) * EB + colBase + cl] = make_float2(b2, b3);
    }
#pragma unroll
    for (int o = 1; o <= 2; o <<= 1) {
        ps0  += __shfl_xor_sync(0xffffffffu, ps0, o);
        pt0  += __shfl_xor_sync(0xffffffffu, pt0, o);
        ps0b += __shfl_xor_sync(0xffffffffu, ps0b, o);
        pt0b += __shfl_xor_sync(0xffffffffu, pt0b, o);
        ps1  += __shfl_xor_sync(0xffffffffu, ps1, o);
        pt1  += __shfl_xor_sync(0xffffffffu, pt1, o);
        ps1b += __shfl_xor_sync(0xffffffffu, ps1b, o);
        pt1b += __shfl_xor_sync(0xffffffffu, pt1b, o);
    }
    if (tig == 0) {
        int rl = warpRow * 16 + gq;
        sredPs[warpCol][rl]      = ps0;   sredPt[warpCol][rl]      = pt0;
        sredPs[warpCol][rl + 8]  = ps0b;  sredPt[warpCol][rl + 8]  = pt0b;
        sredPs[warpCol][rl + 64] = ps1;   sredPt[warpCol][rl + 64] = pt1;
        sredPs[warpCol][rl + 72] = ps1b;  sredPt[warpCol][rl + 72] = pt1b;
    }
    __syncthreads();
    if (tid < 128) {
        int r = rowBase + tid;
        int n = r / AB, a = r % AB;
        float ps = sredPs[0][tid] + sredPs[1][tid];
        float pt = sredPt[0][tid] + sredPt[1][tid];
        int idx = (n * HB + h) * AB + a;
        g_es [idx] = __expf(ps);
        g_es2[idx] = __expf(0.2f * ps);
        g_PQ [idx] = make_float2(__expf(pt), __expf(0.2f * pt));
    }
}

// ---------------- diagonal attention coefficient (64-row tiles, cp.async staged) ----------------
__global__ void attn_k() {
    __shared__ float2 sPQ[AB];
    __shared__ unsigned sEw[ATILE * WORDS];
    __shared__ float sEs[ATILE], sEs2[ATILE], sInv[ATILE];
    int b = blockIdx.x;
    int atile = b % (AB / ATILE);
    int nh = b / (AB / ATILE);
    int n = nh / HB;
    int base = nh * AB;
    int tid = threadIdx.x;
    int a0 = atile * ATILE;

    {
        unsigned dPQ = su32(sPQ), dEw = su32(sEw);
        const char* srcPQ = (const char*)(g_PQ + base);
        const char* srcEw = (const char*)(g_ebits + (size_t)(n * AB + a0) * WORDS);
        for (int c = tid; c < 672; c += 256) {
            CP16(dPQ + c * 16, srcPQ + c * 16);
            CP16(dEw + c * 16, srcEw + c * 16);
        }
    }
    if (tid < ATILE) {
        float es = g_es[base + a0 + tid];
        sEs[tid] = es;
        sEs2[tid] = g_es2[base + a0 + tid];
        sInv[tid] = 1.0f / es;
    }
    asm volatile("cp.async.commit_group;");
    asm volatile("cp.async.wait_group 0;");
    __syncthreads();

    int wid = tid >> 5, lane = tid & 31;
#pragma unroll
    for (int p = 0; p < 4; p++) {
        int r0 = wid * 8 + p * 2;
        int r1 = r0 + 1;
        float inv0 = sInv[r0], inv1 = sInv[r1];
        const unsigned* e0 = &sEw[r0 * WORDS];
        const unsigned* e1 = &sEw[r1 * WORDS];
        float sp0 = 0.f, sq0 = 0.f, sp1 = 0.f, sq1 = 0.f;
#pragma unroll
        for (int it = 0; it < WORDS; it++) {
            float2 pq = sPQ[it * 32 + lane];
            unsigned w0 = e0[it], w1 = e1[it];
            bool cc0 = (w0 >> lane) & 1u;
            bool cc1 = (w1 >> lane) & 1u;
            if (cc0) { if (pq.x > inv0) sp0 += pq.x; else sq0 += pq.y; }
            if (cc1) { if (pq.x > inv1) sp1 += pq.x; else sq1 += pq.y; }
        }
#pragma unroll
        for (int o = 16; o; o >>= 1) {
            sp0 += __shfl_xor_sync(0xffffffffu, sp0, o);
            sq0 += __shfl_xor_sync(0xffffffffu, sq0, o);
            sp1 += __shfl_xor_sync(0xffffffffu, sp1, o);
            sq1 += __shfl_xor_sync(0xffffffffu, sq1, o);
        }
        if (lane < 2) {
            int r = r0 + lane;
            float sp = lane ? sp1 : sp0;
            float sq = lane ? sq1 : sq0;
            int a = a0 + r;
            float es = sEs[r], es2 = sEs2[r];
            float S = es * sp + es2 * sq;
            unsigned selfb = sEw[r * WORDS + (a >> 5)] & (1u << (a & 31));
            float num = 0.f;
            if (selfb) {
                float2 pqa = sPQ[a];
                num = (pqa.x > sInv[r]) ? es * pqa.x : es2 * pqa.y;
            }
            g_diag[base + a] = num / S;
        }
    }
}

// ---------------- epilogue: cp.async-staged 16-row blocks, warp-per-row LN ----------------
__global__ void __launch_bounds__(512) epi_k(
    const float* __restrict__ xin, float* __restrict__ xout,
    const float* __restrict__ lng, const float* __restrict__ lnb,
    const float* __restrict__ bias, const int* __restrict__ mask,
    float* __restrict__ out, int lastLayer)
{
    extern __shared__ float sfp[];    // 16 rows of g_fp = 64KB
    int tid = threadIdx.x;
    int rowBase = blockIdx.x * 16;

    {
        unsigned dst = su32(sfp);
        const char* src = (const char*)(g_fp + (size_t)rowBase * EB);
#pragma unroll
        for (int i = 0; i < 8; i++) {
            int c = tid + i * 512;     // 4096 chunks
            CP16(dst + c * 16, src + (size_t)c * 16);
        }
    }
    asm volatile("cp.async.commit_group;");
    asm volatile("cp.async.wait_group 0;");
    __syncthreads();

    int wid = tid >> 5, lane = tid & 31;
    int row = rowBase + wid;
    int n = row / AB, a = row % AB;

    float dg0 = 0.f;
    if (lane < 8) dg0 = g_diag[(n * HB + lane) * AB + a];

    float4 gg = *(const float4*)&lng[lane * 4];
    float4 bb = *(const float4*)&lnb[lane * 4];
    float4 bs = *(const float4*)&bias[lane * 4];

    float4 acc = make_float4(0.f, 0.f, 0.f, 0.f);
#pragma unroll
    for (int h = 0; h < HB; h++) {
        float dg = __shfl_sync(0xffffffffu, dg0, h);
        float4 u = *(const float4*)&sfp[wid * EB + h * DB + lane * 4];
        u.x *= dg; u.y *= dg; u.z *= dg; u.w *= dg;
        float sum = u.x + u.y + u.z + u.w;
        float ss = u.x*u.x + u.y*u.y + u.z*u.z + u.w*u.w;
#pragma unroll
        for (int o = 16; o; o >>= 1) {
            sum += __shfl_xor_sync(0xffffffffu, sum, o);
            ss  += __shfl_xor_sync(0xffffffffu, ss, o);
        }
        float mu = sum * (1.f / 128.f);
        float var = ss * (1.f / 128.f) - mu * mu;
        float rstd = rsqrtf(var + 1e-5f);
        acc.x += (u.x - mu) * rstd * gg.x + bb.x;
        acc.y += (u.y - mu) * rstd * gg.y + bb.y;
        acc.z += (u.z - mu) * rstd * gg.z + bb.z;
        acc.w += (u.w - mu) * rstd * gg.w + bb.w;
    }
    float4 fin = *(const float4*)&xin[(size_t)row * DB + lane * 4];
    float4 o4;
    o4.x = acc.x * 0.125f + fin.x + bs.x;
    o4.y = acc.y * 0.125f + fin.y + bs.y;
    o4.z = acc.z * 0.125f + fin.z + bs.z;
    o4.w = acc.w * 0.125f + fin.w + bs.w;

    if (!lastLayer) {
        size_t ob = (size_t)row * DB + lane * 4;
        *(float4*)&xout[ob] = o4;
        __nv_bfloat16 h0 = __float2bfloat16(o4.x), h1 = __float2bfloat16(o4.y);
        __nv_bfloat16 h2 = __float2bfloat16(o4.z), h3 = __float2bfloat16(o4.w);
        *(__nv_bfloat162*)&g_xhi[ob]   = __halves2bfloat162(h0, h1);
        *(__nv_bfloat162*)&g_xhi[ob+2] = __halves2bfloat162(h2, h3);
        *(__nv_bfloat162*)&g_xlo[ob] = __halves2bfloat162(
            __float2bfloat16(o4.x - __bfloat162float(h0)),
            __float2bfloat16(o4.y - __bfloat162float(h1)));
        *(__nv_bfloat162*)&g_xlo[ob+2] = __halves2bfloat162(
            __float2bfloat16(o4.z - __bfloat162float(h2)),
            __float2bfloat16(o4.w - __bfloat162float(h3)));
    } else if (mask[row] != 0) {
        int lres = a / ATOMS;
        float* dst = &out[(size_t)(n * LB + lres) * DB + lane * 4];
        atomicAdd(dst,     o4.x);
        atomicAdd(dst + 1, o4.y);
        atomicAdd(dst + 2, o4.z);
        atomicAdd(dst + 3, o4.w);
    }
}

// ---------------- launch ----------------
extern "C" void kernel_launch(void* const* d_in, const int* in_sizes, int n_in,
                              void* d_out, int out_size) {
    const float*    feats = (const float*)d_in[0];
    const int*      mask  = (const int*)d_in[1];
    const unsigned* emask = (const unsigned*)d_in[2];
    const float*    W     = (const float*)d_in[3];
    const float*    ssrc  = (const float*)d_in[4];
    const float*    stag  = (const float*)d_in[5];
    const float*    bias  = (const float*)d_in[6];
    const float*    lng   = (const float*)d_in[7];
    const float*    lnb   = (const float*)d_in[8];
    float* out = (float*)d_out;

    cudaFuncSetAttribute(gemm_fp_k, cudaFuncAttributeMaxDynamicSharedMemorySize, GSMEM);
    cudaFuncSetAttribute(epi_k, cudaFuncAttributeMaxDynamicSharedMemorySize, ESMEM);

    float *px0 = nullptr, *px1 = nullptr;
    __nv_bfloat16 *pxhi = nullptr, *pxlo = nullptr, *pwhi = nullptr, *pwlo = nullptr;
    cudaGetSymbolAddress((void**)&px0, g_x0);
    cudaGetSymbolAddress((void**)&px1, g_x1);
    cudaGetSymbolAddress((void**)&pxhi, g_xhi);
    cudaGetSymbolAddress((void**)&pxlo, g_xlo);
    cudaGetSymbolAddress((void**)&pwhi, g_whi);
    cudaGetSymbolAddress((void**)&pwlo, g_wlo);

    setup_k<<<PACK_BLKS + CONVW_BLKS + CONVX_BLKS + OUTZ_BLKS, 256>>>(
        emask, W, feats, pwhi, pwlo, pxhi, pxlo, out);

    const float* xin = feats;
    float* bufs[2] = {px0, px1};
    for (int l = 0; l < DEPTH; l++) {
        float* xout = bufs[l & 1];
        gemm_fp_k<<<dim3(RB / 128, HB), 256, GSMEM>>>(
            pxhi, pxlo,
            pwhi + (size_t)l * EB * DB, pwlo + (size_t)l * EB * DB,
            mask, ssrc + l * HB * DB, stag + l * HB * DB);
        attn_k<<<NB * HB * (AB / ATILE), 256>>>();
        epi_k<<<RB / 16, 512, ESMEM>>>(xin, xout, lng + l * DB, lnb + l * DB, bias + l * DB,
                                       mask, out, (l == DEPTH - 1) ? 1 : 0);
        xin = xout;
    }
}

// round 16
// speedup vs baseline: 1.0769x; 1.0769x over previous
#include <cuda_runtime.h>
#include <cuda_bf16.h>
#include <cstdint>

#define NB 2
#define AB 1344
#define LB 96
#define ATOMS 14
#define DB 128
#define HB 8
#define DEPTH 3
#define RB (NB*AB)      /* 2688 */
#define EB (HB*DB)      /* 1024 */
#define WORDS (AB/32)   /* 42 */
#define ATILE 64
#define LDSB 136
#define GSMEM ((128+128)*LDSB*2)    /* 69632 */

#define PACK_BLKS ((NB*AB*WORDS)/8) /* 14112 */
#define CONVW_N4 (DEPTH*EB*DB/4)
#define CONVW_BLKS ((CONVW_N4+255)/256)
#define CONVX_N4 (RB*DB/4)
#define CONVX_BLKS ((CONVX_N4+255)/256)
#define OUTZ_N4 (NB*LB*DB/4)        /* 6144 */
#define OUTZ_BLKS ((OUTZ_N4+255)/256)

// ---------------- scratch ----------------
__device__ float  g_fp[RB*EB];
__device__ float  g_x0[RB*DB];
__device__ float  g_x1[RB*DB];
__device__ __nv_bfloat16 g_xhi[RB*DB];
__device__ __nv_bfloat16 g_xlo[RB*DB];
__device__ __nv_bfloat16 g_whi[DEPTH*EB*DB];
__device__ __nv_bfloat16 g_wlo[DEPTH*EB*DB];
__device__ float  g_es [NB*HB*AB];
__device__ float  g_es2[NB*HB*AB];
__device__ float2 g_PQ [NB*HB*AB];
__device__ float  g_diag[NB*HB*AB];
__device__ unsigned g_ebits[NB*AB*WORDS];

#define LDSM4(r0,r1,r2,r3,addr) asm volatile( \
  "ldmatrix.sync.aligned.m8n8.x4.shared.b16 {%0,%1,%2,%3}, [%4];" \
  : "=r"(r0),"=r"(r1),"=r"(r2),"=r"(r3) : "r"(addr))

#define MMA_BF16(c,a0,a1,a2,a3,b0,b1) asm volatile( \
  "mma.sync.aligned.m16n8k16.row.col.f32.bf16.bf16.f32 " \
  "{%0,%1,%2,%3},{%4,%5,%6,%7},{%8,%9},{%0,%1,%2,%3};" \
  : "+f"(c[0]),"+f"(c[1]),"+f"(c[2]),"+f"(c[3]) \
  : "r"(a0),"r"(a1),"r"(a2),"r"(a3),"r"(b0),"r"(b1))

#define CP16(dst_u32, src_ptr) asm volatile( \
  "cp.async.cg.shared.global [%0], [%1], 16;" :: "r"(dst_u32), "l"(src_ptr))

__device__ __forceinline__ unsigned su32(const void* p) {
    unsigned a;
    asm("{ .reg .u64 t; cvta.to.shared.u64 t, %1; cvt.u32.u64 %0, t; }" : "=r"(a) : "l"(p));
    return a;
}

// ---------------- fused setup: pack edges + hi/lo convs + zero out ----------------
__device__ __forceinline__ void conv4(const float* __restrict__ src,
                                      __nv_bfloat16* __restrict__ hi,
                                      __nv_bfloat16* __restrict__ lo, int idx) {
    float4 v = ((const float4*)src)[idx];
    __nv_bfloat16 h0 = __float2bfloat16(v.x), h1 = __float2bfloat16(v.y);
    __nv_bfloat16 h2 = __float2bfloat16(v.z), h3 = __float2bfloat16(v.w);
    __nv_bfloat16 l0 = __float2bfloat16(v.x - __bfloat162float(h0));
    __nv_bfloat16 l1 = __float2bfloat16(v.y - __bfloat162float(h1));
    __nv_bfloat16 l2 = __float2bfloat16(v.z - __bfloat162float(h2));
    __nv_bfloat16 l3 = __float2bfloat16(v.w - __bfloat162float(h3));
    ((__nv_bfloat162*)hi)[idx*2]   = __halves2bfloat162(h0, h1);
    ((__nv_bfloat162*)hi)[idx*2+1] = __halves2bfloat162(h2, h3);
    ((__nv_bfloat162*)lo)[idx*2]   = __halves2bfloat162(l0, l1);
    ((__nv_bfloat162*)lo)[idx*2+1] = __halves2bfloat162(l2, l3);
}

__global__ void setup_k(const unsigned* __restrict__ em, const float* __restrict__ W,
                        const float* __restrict__ feats,
                        __nv_bfloat16* __restrict__ whi, __nv_bfloat16* __restrict__ wlo,
                        __nv_bfloat16* __restrict__ xhi, __nv_bfloat16* __restrict__ xlo,
                        float* __restrict__ out) {
    int b = blockIdx.x;
    int tid = threadIdx.x;
    if (b < PACK_BLKS) {
        int w = b * 8 + (tid >> 5);
        int lane = tid & 31;
        unsigned v = em[(size_t)w * 32 + lane];
        unsigned m = __ballot_sync(0xffffffffu, v != 0u);
        if (lane == 0) g_ebits[w] = m;
    } else if (b < PACK_BLKS + CONVW_BLKS) {
        int idx = (b - PACK_BLKS) * 256 + tid;
        if (idx < CONVW_N4) conv4(W, whi, wlo, idx);
    } else if (b < PACK_BLKS + CONVW_BLKS + CONVX_BLKS) {
        int idx = (b - PACK_BLKS - CONVW_BLKS) * 256 + tid;
        if (idx < CONVX_N4) conv4(feats, xhi, xlo, idx);
    } else {
        int idx = (b - PACK_BLKS - CONVW_BLKS - CONVX_BLKS) * 256 + tid;
        if (idx < OUTZ_N4) ((float4*)out)[idx] = make_float4(0.f, 0.f, 0.f, 0.f);
    }
}

// ---------------- TC GEMM: 64 rows x 128 cols (one head), B buffer reloaded ----------------
__global__ void __launch_bounds__(256, 3) gemm_fp_k(
    const __nv_bfloat16* __restrict__ Xhi, const __nv_bfloat16* __restrict__ Xlo,
    const __nv_bfloat16* __restrict__ Whi, const __nv_bfloat16* __restrict__ Wlo,
    const int* __restrict__ mask,
    const float* __restrict__ ssrc, const float* __restrict__ stag)
{
    extern __shared__ __nv_bfloat16 sm[];
    __nv_bfloat16* Ahi = sm;
    __nv_bfloat16* Alo = sm + 64 * LDSB;
    __nv_bfloat16* Bb  = sm + 128 * LDSB;
    __shared__ float sws[128], swt[128];
    __shared__ float sredPs[2][64], sredPt[2][64];

    int tid = threadIdx.x;
    int rowBase = blockIdx.x * 64;
    int h = blockIdx.y;
    int colBase = h * DB;

    if (tid < 128) { sws[tid] = ssrc[colBase + tid]; swt[tid] = stag[colBase + tid]; }

    unsigned sAhi = (unsigned)__cvta_generic_to_shared(Ahi);
    unsigned sAlo = (unsigned)__cvta_generic_to_shared(Alo);
    unsigned sB   = (unsigned)__cvta_generic_to_shared(Bb);

#pragma unroll
    for (int i = 0; i < 4; i++) {
        int c = tid + i * 256;
        int r = c >> 4, col = (c & 15) * 8;
        size_t goff = (size_t)(rowBase + r) * 128 + col;
        unsigned so = (r * LDSB + col) * 2;
        CP16(sAhi + so, Xhi + goff);
        CP16(sAlo + so, Xlo + goff);
    }
#pragma unroll
    for (int i = 0; i < 8; i++) {
        int c = tid + i * 256;
        int r = c >> 4, col = (c & 15) * 8;
        size_t goff = (size_t)(h * 128 + r) * 128 + col;
        CP16(sB + (r * LDSB + col) * 2, Whi + goff);
    }
    asm volatile("cp.async.commit_group;");
    asm volatile("cp.async.wait_group 0;");
    __syncthreads();

    int wid = tid >> 5, lane = tid & 31;
    int warpRow = wid & 3, warpCol = wid >> 2;
    int gq = lane >> 2, tig = lane & 3;

    unsigned aoff = ((warpRow * 16 + (lane & 15)) * LDSB + (lane >> 4) * 8) * 2;
    unsigned boff = ((warpCol * 64 + (lane & 7) + (lane >> 4) * 8) * LDSB
                     + ((lane >> 3) & 1) * 8) * 2;
    unsigned aHiB = sAhi + aoff;
    unsigned aLoB = sAlo + aoff;
    unsigned bB   = sB + boff;

    float c[8][4];
#pragma unroll
    for (int t = 0; t < 8; t++)
#pragma unroll
        for (int j = 0; j < 4; j++) c[t][j] = 0.f;

    // pass 1: B = Whi; Ahi*Bhi + Alo*Bhi
#pragma unroll
    for (int ks = 0; ks < 8; ks++) {
        unsigned kb = ks * 32;
        unsigned a0, a1, a2, a3, e0, e1, e2, e3;
        LDSM4(a0, a1, a2, a3, aHiB + kb);
        LDSM4(e0, e1, e2, e3, aLoB + kb);
        unsigned bh[16];
#pragma unroll
        for (int g4 = 0; g4 < 4; g4++) {
            unsigned off = g4 * 16 * LDSB * 2 + kb;
            LDSM4(bh[g4*4], bh[g4*4+1], bh[g4*4+2], bh[g4*4+3], bB + off);
        }
#pragma unroll
        for (int t = 0; t < 8; t++) {
            int bi = (t >> 1) * 4 + (t & 1) * 2;
            MMA_BF16(c[t], a0, a1, a2, a3, bh[bi], bh[bi+1]);
            MMA_BF16(c[t], e0, e1, e2, e3, bh[bi], bh[bi+1]);
        }
    }
    __syncthreads();

    // reload B = Wlo
#pragma unroll
    for (int i = 0; i < 8; i++) {
        int cc = tid + i * 256;
        int r = cc >> 4, col = (cc & 15) * 8;
        size_t goff = (size_t)(h * 128 + r) * 128 + col;
        CP16(sB + (r * LDSB + col) * 2, Wlo + goff);
    }
    asm volatile("cp.async.commit_group;");
    asm volatile("cp.async.wait_group 0;");
    __syncthreads();

    // pass 2: Ahi * Blo
#pragma unroll
    for (int ks = 0; ks < 8; ks++) {
        unsigned kb = ks * 32;
        unsigned a0, a1, a2, a3;
        LDSM4(a0, a1, a2, a3, aHiB + kb);
        unsigned bh[16];
#pragma unroll
        for (int g4 = 0; g4 < 4; g4++) {
            unsigned off = g4 * 16 * LDSB * 2 + kb;
            LDSM4(bh[g4*4], bh[g4*4+1], bh[g4*4+2], bh[g4*4+3], bB + off);
        }
#pragma unroll
        for (int t = 0; t < 8; t++) {
            int bi = (t >> 1) * 4 + (t & 1) * 2;
            MMA_BF16(c[t], a0, a1, a2, a3, bh[bi], bh[bi+1]);
        }
    }

    // epilogue
    int rA = rowBase + warpRow * 16 + gq;
    int rBp = rA + 8;
    float mA = (mask[rA]  != 0) ? 1.f : 0.f;
    float mB = (mask[rBp] != 0) ? 1.f : 0.f;
    float psA = 0.f, ptA = 0.f, psB = 0.f, ptB = 0.f;
#pragma unroll
    for (int t = 0; t < 8; t++) {
        int cl = warpCol * 64 + t * 8 + tig * 2;
        float w0s = sws[cl], w1s = sws[cl+1], w0t = swt[cl], w1t = swt[cl+1];
        float c0 = c[t][0] * mA, c1 = c[t][1] * mA;
        float c2 = c[t][2] * mB, c3 = c[t][3] * mB;
        psA += c0 * w0s + c1 * w1s;  ptA += c0 * w0t + c1 * w1t;
        psB += c2 * w0s + c3 * w1s;  ptB += c2 * w0t + c3 * w1t;
        *(float2*)&g_fp[(size_t)rA  * EB + colBase + cl] = make_float2(c0, c1);
        *(float2*)&g_fp[(size_t)rBp * EB + colBase + cl] = make_float2(c2, c3);
    }
#pragma unroll
    for (int o = 1; o <= 2; o <<= 1) {
        psA += __shfl_xor_sync(0xffffffffu, psA, o);
        ptA += __shfl_xor_sync(0xffffffffu, ptA, o);
        psB += __shfl_xor_sync(0xffffffffu, psB, o);
        ptB += __shfl_xor_sync(0xffffffffu, ptB, o);
    }
    if (tig == 0) {
        int rl = warpRow * 16 + gq;
        sredPs[warpCol][rl]     = psA;  sredPt[warpCol][rl]     = ptA;
        sredPs[warpCol][rl + 8] = psB;  sredPt[warpCol][rl + 8] = ptB;
    }
    __syncthreads();
    if (tid < 64) {
        int r = rowBase + tid;
        int n = r / AB, a = r % AB;
        float ps = sredPs[0][tid] + sredPs[1][tid];
        float pt = sredPt[0][tid] + sredPt[1][tid];
        int idx = (n * HB + h) * AB + a;
        g_es [idx] = __expf(ps);
        g_es2[idx] = __expf(0.2f * ps);
        g_PQ [idx] = make_float2(__expf(pt), __expf(0.2f * pt));
    }
}

// ---------------- diagonal attention coefficient (64-row tiles, cp.async staged) ----------------
__global__ void attn_k() {
    __shared__ float2 sPQ[AB];
    __shared__ unsigned sEw[ATILE * WORDS];
    __shared__ float sEs[ATILE], sEs2[ATILE], sInv[ATILE];
    int b = blockIdx.x;
    int atile = b % (AB / ATILE);
    int nh = b / (AB / ATILE);
    int n = nh / HB;
    int base = nh * AB;
    int tid = threadIdx.x;
    int a0 = atile * ATILE;

    {
        unsigned dPQ = su32(sPQ), dEw = su32(sEw);
        const char* srcPQ = (const char*)(g_PQ + base);
        const char* srcEw = (const char*)(g_ebits + (size_t)(n * AB + a0) * WORDS);
        for (int c = tid; c < 672; c += 256) {
            CP16(dPQ + c * 16, srcPQ + c * 16);
            CP16(dEw + c * 16, srcEw + c * 16);
        }
    }
    if (tid < ATILE) {
        float es = g_es[base + a0 + tid];
        sEs[tid] = es;
        sEs2[tid] = g_es2[base + a0 + tid];
        sInv[tid] = 1.0f / es;
    }
    asm volatile("cp.async.commit_group;");
    asm volatile("cp.async.wait_group 0;");
    __syncthreads();

    int wid = tid >> 5, lane = tid & 31;
#pragma unroll
    for (int p = 0; p < 4; p++) {
        int r0 = wid * 8 + p * 2;
        int r1 = r0 + 1;
        float inv0 = sInv[r0], inv1 = sInv[r1];
        const unsigned* e0 = &sEw[r0 * WORDS];
        const unsigned* e1 = &sEw[r1 * WORDS];
        float sp0 = 0.f, sq0 = 0.f, sp1 = 0.f, sq1 = 0.f;
#pragma unroll
        for (int it = 0; it < WORDS; it++) {
            float2 pq = sPQ[it * 32 + lane];
            unsigned w0 = e0[it], w1 = e1[it];
            bool c0 = (w0 >> lane) & 1u;
            bool c1 = (w1 >> lane) & 1u;
            if (c0) { if (pq.x > inv0) sp0 += pq.x; else sq0 += pq.y; }
            if (c1) { if (pq.x > inv1) sp1 += pq.x; else sq1 += pq.y; }
        }
#pragma unroll
        for (int o = 16; o; o >>= 1) {
            sp0 += __shfl_xor_sync(0xffffffffu, sp0, o);
            sq0 += __shfl_xor_sync(0xffffffffu, sq0, o);
            sp1 += __shfl_xor_sync(0xffffffffu, sp1, o);
            sq1 += __shfl_xor_sync(0xffffffffu, sq1, o);
        }
        if (lane < 2) {
            int r = r0 + lane;
            float sp = lane ? sp1 : sp0;
            float sq = lane ? sq1 : sq0;
            int a = a0 + r;
            float es = sEs[r], es2 = sEs2[r];
            float S = es * sp + es2 * sq;
            unsigned selfb = sEw[r * WORDS + (a >> 5)] & (1u << (a & 31));
            float num = 0.f;
            if (selfb) {
                float2 pqa = sPQ[a];
                num = (pqa.x > sInv[r]) ? es * pqa.x : es2 * pqa.y;
            }
            g_diag[base + a] = num / S;
        }
    }
}

// ---------------- epilogue: WARP-LOCAL cp.async staging, warp-per-row LN ----------------
__global__ void __launch_bounds__(256) epi_k(
    const float* __restrict__ xin, float* __restrict__ xout,
    const float* __restrict__ lng, const float* __restrict__ lnb,
    const float* __restrict__ bias, const int* __restrict__ mask,
    float* __restrict__ out, int lastLayer)
{
    __shared__ float sfp[8 * EB];     // 32KB: 8 rows of g_fp
    int tid = threadIdx.x;
    int wid = tid >> 5, lane = tid & 31;
    int rowBase = blockIdx.x * 8;
    int row = rowBase + wid;
    int n = row / AB, a = row % AB;

    // warp-local staging: each warp stages ONLY its own row (4KB = 256 chunks, 8/lane)
    {
        unsigned dst = su32(&sfp[wid * EB]);
        const char* src = (const char*)(g_fp + (size_t)row * EB);
#pragma unroll
        for (int i = 0; i < 8; i++) {
            int c = lane + i * 32;
            CP16(dst + c * 16, src + (size_t)c * 16);
        }
    }
    asm volatile("cp.async.commit_group;");

    // overlap: fetch per-row scalars while the row streams in
    float dg0 = 0.f;
    if (lane < 8) dg0 = g_diag[(n * HB + lane) * AB + a];
    float4 gg = *(const float4*)&lng[lane * 4];
    float4 bb = *(const float4*)&lnb[lane * 4];
    float4 bs = *(const float4*)&bias[lane * 4];
    float4 fin = *(const float4*)&xin[(size_t)row * DB + lane * 4];

    asm volatile("cp.async.wait_group 0;");
    __syncwarp();

    float4 acc = make_float4(0.f, 0.f, 0.f, 0.f);
#pragma unroll
    for (int h = 0; h < HB; h++) {
        float dg = __shfl_sync(0xffffffffu, dg0, h);
        float4 u = *(const float4*)&sfp[wid * EB + h * DB + lane * 4];
        u.x *= dg; u.y *= dg; u.z *= dg; u.w *= dg;
        float sum = u.x + u.y + u.z + u.w;
        float ss = u.x*u.x + u.y*u.y + u.z*u.z + u.w*u.w;
#pragma unroll
        for (int o = 16; o; o >>= 1) {
            sum += __shfl_xor_sync(0xffffffffu, sum, o);
            ss  += __shfl_xor_sync(0xffffffffu, ss, o);
        }
        float mu = sum * (1.f / 128.f);
        float var = ss * (1.f / 128.f) - mu * mu;
        float rstd = rsqrtf(var + 1e-5f);
        acc.x += (u.x - mu) * rstd * gg.x + bb.x;
        acc.y += (u.y - mu) * rstd * gg.y + bb.y;
        acc.z += (u.z - mu) * rstd * gg.z + bb.z;
        acc.w += (u.w - mu) * rstd * gg.w + bb.w;
    }
    float4 o4;
    o4.x = acc.x * 0.125f + fin.x + bs.x;
    o4.y = acc.y * 0.125f + fin.y + bs.y;
    o4.z = acc.z * 0.125f + fin.z + bs.z;
    o4.w = acc.w * 0.125f + fin.w + bs.w;

    if (!lastLayer) {
        size_t ob = (size_t)row * DB + lane * 4;
        *(float4*)&xout[ob] = o4;
        __nv_bfloat16 h0 = __float2bfloat16(o4.x), h1 = __float2bfloat16(o4.y);
        __nv_bfloat16 h2 = __float2bfloat16(o4.z), h3 = __float2bfloat16(o4.w);
        *(__nv_bfloat162*)&g_xhi[ob]   = __halves2bfloat162(h0, h1);
        *(__nv_bfloat162*)&g_xhi[ob+2] = __halves2bfloat162(h2, h3);
        *(__nv_bfloat162*)&g_xlo[ob] = __halves2bfloat162(
            __float2bfloat16(o4.x - __bfloat162float(h0)),
            __float2bfloat16(o4.y - __bfloat162float(h1)));
        *(__nv_bfloat162*)&g_xlo[ob+2] = __halves2bfloat162(
            __float2bfloat16(o4.z - __bfloat162float(h2)),
            __float2bfloat16(o4.w - __bfloat162float(h3)));
    } else if (mask[row] != 0) {
        int lres = a / ATOMS;
        float* dst = &out[(size_t)(n * LB + lres) * DB + lane * 4];
        atomicAdd(dst,     o4.x);
        atomicAdd(dst + 1, o4.y);
        atomicAdd(dst + 2, o4.z);
        atomicAdd(dst + 3, o4.w);
    }
}

// ---------------- launch ----------------
extern "C" void kernel_launch(void* const* d_in, const int* in_sizes, int n_in,
                              void* d_out, int out_size) {
    const float*    feats = (const float*)d_in[0];
    const int*      mask  = (const int*)d_in[1];
    const unsigned* emask = (const unsigned*)d_in[2];
    const float*    W     = (const float*)d_in[3];
    const float*    ssrc  = (const float*)d_in[4];
    const float*    stag  = (const float*)d_in[5];
    const float*    bias  = (const float*)d_in[6];
    const float*    lng   = (const float*)d_in[7];
    const float*    lnb   = (const float*)d_in[8];
    float* out = (float*)d_out;

    cudaFuncSetAttribute(gemm_fp_k, cudaFuncAttributeMaxDynamicSharedMemorySize, GSMEM);

    float *px0 = nullptr, *px1 = nullptr;
    __nv_bfloat16 *pxhi = nullptr, *pxlo = nullptr, *pwhi = nullptr, *pwlo = nullptr;
    cudaGetSymbolAddress((void**)&px0, g_x0);
    cudaGetSymbolAddress((void**)&px1, g_x1);
    cudaGetSymbolAddress((void**)&pxhi, g_xhi);
    cudaGetSymbolAddress((void**)&pxlo, g_xlo);
    cudaGetSymbolAddress((void**)&pwhi, g_whi);
    cudaGetSymbolAddress((void**)&pwlo, g_wlo);

    setup_k<<<PACK_BLKS + CONVW_BLKS + CONVX_BLKS + OUTZ_BLKS, 256>>>(
        emask, W, feats, pwhi, pwlo, pxhi, pxlo, out);

    const float* xin = feats;
    float* bufs[2] = {px0, px1};
    for (int l = 0; l < DEPTH; l++) {
        float* xout = bufs[l & 1];
        gemm_fp_k<<<dim3(RB / 64, HB), 256, GSMEM>>>(
            pxhi, pxlo,
            pwhi + (size_t)l * EB * DB, pwlo + (size_t)l * EB * DB,
            mask, ssrc + l * HB * DB, stag + l * HB * DB);
        attn_k<<<NB * HB * (AB / ATILE), 256>>>();
        epi_k<<<RB / 8, 256>>>(xin, xout, lng + l * DB, lnb + l * DB, bias + l * DB,
                               mask, out, (l == DEPTH - 1) ? 1 : 0);
        xin = xout;
    }
}